// round 15
// baseline (speedup 1.0000x reference)
#include <cuda_runtime.h>
#include <cuda_fp16.h>
#include <stdint.h>
#include <math.h>

#define BB 4
#define SS 4096
#define DD 1024
#define MPROJ (BB*SS)

// ---------------- device scratch ----------------
__device__ __half g_x16[(size_t)MPROJ*DD];
__device__ __half g_w16[(size_t)DD*3*DD];        // [K=1024, N=3072] = [Wq|Wk|Wv] cols
__device__ __half g_q16[(size_t)MPROJ*DD];
__device__ __half g_k16[(size_t)MPROJ*DD];
__device__ __half g_v16[(size_t)MPROJ*DD];
__device__ __half g_p16[(size_t)BB*SS*SS];
__device__ float  g_part[(size_t)BB*SS*32];
__device__ float  g_rsum[(size_t)BB*SS];

// ---------------- PTX helpers (sm_80-level; no 'a'-suffix features) ----------------
__device__ __forceinline__ uint32_t smem_u32(const void* p) {
    uint32_t a;
    asm("{ .reg .u64 t; cvta.to.shared.u64 t, %1; cvt.u32.u64 %0, t; }" : "=r"(a) : "l"(p));
    return a;
}
__device__ __forceinline__ void cp_async16(uint32_t dst, const void* src) {
    asm volatile("cp.async.cg.shared.global [%0], [%1], 16;" :: "r"(dst), "l"(src));
}
__device__ __forceinline__ void cp_commit() {
    asm volatile("cp.async.commit_group;" ::: "memory");
}
template <int N>
__device__ __forceinline__ void cp_wait() {
    asm volatile("cp.async.wait_group %0;" :: "n"(N) : "memory");
}
__device__ __forceinline__ void ldsm_x4(uint32_t* r, uint32_t addr) {
    asm volatile("ldmatrix.sync.aligned.m8n8.x4.shared.b16 {%0,%1,%2,%3}, [%4];"
                 : "=r"(r[0]), "=r"(r[1]), "=r"(r[2]), "=r"(r[3]) : "r"(addr));
}
__device__ __forceinline__ void ldsm_x4_t(uint32_t* r, uint32_t addr) {
    asm volatile("ldmatrix.sync.aligned.m8n8.x4.trans.shared.b16 {%0,%1,%2,%3}, [%4];"
                 : "=r"(r[0]), "=r"(r[1]), "=r"(r[2]), "=r"(r[3]) : "r"(addr));
}
__device__ __forceinline__ void mma_f16(float* c, const uint32_t* a, const uint32_t* b) {
    asm volatile(
        "mma.sync.aligned.m16n8k16.row.col.f32.f16.f16.f32 "
        "{%0,%1,%2,%3}, {%4,%5,%6,%7}, {%8,%9}, {%0,%1,%2,%3};"
        : "+f"(c[0]), "+f"(c[1]), "+f"(c[2]), "+f"(c[3])
        : "r"(a[0]), "r"(a[1]), "r"(a[2]), "r"(a[3]), "r"(b[0]), "r"(b[1]));
}
__device__ __forceinline__ uint32_t pack_h2(float v0, float v1) {
    __half h0 = __float2half_rn(v0);
    __half h1 = __float2half_rn(v1);
    return (uint32_t)__half_as_ushort(h0) | ((uint32_t)__half_as_ushort(h1) << 16);
}

// ===== GEMM: CTA 128x128, BK=64, 2 stages, 2 CTAs/SM, 4 warps (2x2), warp 64x64 ====
// TRB=true : B is [N,K] row-major (NT): B tile 128 n-rows x 128B
// TRB=false: B is [K,N] row-major (NN): B tile 64 k-rows x 256B (ldsm.trans)
#define GBM 128
#define GBN 128
#define GBK 64
#define NTHREADS 128
#define ROWA 128               // bytes per A smem row (64 fp16)
#define ABYTES (GBM*ROWA)      // 16384
#define BOF ABYTES
#define BBYTES 16384
#define STAGEB (ABYTES + BBYTES)   // 32768
#define GEMM_SMEM (2*STAGEB)       // 65536

template <bool TRB>
__device__ __forceinline__ void stage_in(
    const __half* A, const __half* B,
    int ldA, int ldB, int m0, int n0, int k0, uint32_t sb, int tid)
{
#pragma unroll
    for (int i = 0; i < 8; ++i) {             // A: 128 rows x 8 chunks of 16B
        const int idx = tid + i * NTHREADS;
        const int r = idx >> 3, c16 = idx & 7;
        const uint32_t soff = (uint32_t)(r * ROWA + (((c16 ^ (r & 7)) << 4)));
        cp_async16(sb + soff, A + (size_t)(m0 + r) * ldA + k0 + c16 * 8);
    }
    if (TRB) {
#pragma unroll
        for (int i = 0; i < 8; ++i) {         // B: 128 n-rows x 8 chunks
            const int idx = tid + i * NTHREADS;
            const int r = idx >> 3, c16 = idx & 7;
            const uint32_t soff = (uint32_t)(r * ROWA + (((c16 ^ (r & 7)) << 4)));
            cp_async16(sb + BOF + soff, B + (size_t)(n0 + r) * ldB + k0 + c16 * 8);
        }
    } else {
#pragma unroll
        for (int i = 0; i < 8; ++i) {         // B: 64 k-rows x 16 chunks (256B rows)
            const int idx = tid + i * NTHREADS;
            const int r = idx >> 4, c16 = idx & 15;
            const uint32_t soff = (uint32_t)(r * 256 + (((c16 ^ (r & 7)) << 4)));
            cp_async16(sb + BOF + soff, B + (size_t)(k0 + r) * ldB + n0 + c16 * 8);
        }
    }
}

// MODE 1: fp16 outputs routed among q/k/v by global n / 1024 (projection)
// MODE 2: C fp32 = alpha * D / rsum[row]  (PV)
// MODE 3: P = exp(alpha*D) fp16 + per-(row,ctaX) partial sums (QK+softmax)
template <int MODE, bool TRB>
__global__ void __launch_bounds__(NTHREADS, 2)
tc_gemm(const __half* __restrict__ A, const __half* __restrict__ B,
        float* __restrict__ Cf,
        __half* __restrict__ o0, __half* __restrict__ o1, __half* __restrict__ o2,
        int M, int N, int K, int ldA, int ldB,
        size_t zA, size_t zB, size_t zC,
        float alpha, const float* __restrict__ rsum, float* __restrict__ part)
{
    extern __shared__ __align__(128) char smem[];
    const uint32_t sbase = smem_u32(smem);
    const int tid = threadIdx.x;
    const int wid = tid >> 5, lane = tid & 31;
    const int wm = wid >> 1, wn = wid & 1;        // warp grid 2(m) x 2(n), warp 64x64
    const int z = blockIdx.z;
    const int m0 = blockIdx.y * GBM, n0 = blockIdx.x * GBN;

    A += (size_t)z * zA;  B += (size_t)z * zB;

    float acc[4][8][4];
#pragma unroll
    for (int i = 0; i < 4; ++i)
#pragma unroll
        for (int j = 0; j < 8; ++j)
#pragma unroll
            for (int q = 0; q < 4; ++q) acc[i][j][q] = 0.f;

    const int numT = K / GBK;
    stage_in<TRB>(A, B, ldA, ldB, m0, n0, 0, sbase, tid);
    cp_commit();

    // A fragment addressing (plain ldsm): warp rows wm*64 .. +63
    const int a_row = wm * 64 + (lane & 15);
    const uint32_t a_rl = (uint32_t)(a_row & 7);
    const uint32_t a_hi4 = (uint32_t)(lane >> 4);
    const uint32_t a_off = (uint32_t)(a_row * ROWA);

    // B fragment addressing — NT path: warp cols wn*64 .. +63
    const int b_row = wn * 64 + ((lane >> 4) & 1) * 8 + (lane & 7);
    const uint32_t b_rl = (uint32_t)(b_row & 7);
    const uint32_t b_hi = (uint32_t)((lane >> 3) & 1);
    const uint32_t b_off = (uint32_t)(b_row * ROWA);

    // B fragment addressing — NN (trans) path
    const uint32_t t_klocal = (uint32_t)(((lane >> 3) & 1) * 8 + (lane & 7));
    const uint32_t t_rl = (uint32_t)(lane & 7);
    const uint32_t t_hi = (uint32_t)(lane >> 4);

    for (int t = 0; t < numT; ++t) {
        if (t + 1 < numT) {
            stage_in<TRB>(A, B, ldA, ldB, m0, n0, (t + 1) * GBK,
                          sbase + ((t + 1) & 1) * STAGEB, tid);
            cp_commit();
            cp_wait<1>();
        } else {
            cp_wait<0>();
        }
        __syncthreads();

        const uint32_t sbuf = sbase + (t & 1) * STAGEB;
#pragma unroll
        for (int kc = 0; kc < 4; ++kc) {
            uint32_t af[4][4], bf[8][2];
            const uint32_t a_x = ((((uint32_t)(kc * 2) + a_hi4) ^ a_rl) << 4);
#pragma unroll
            for (int mt = 0; mt < 4; ++mt)
                ldsm_x4(af[mt], sbuf + a_off + a_x + mt * (16 * ROWA));

            if (TRB) {
                const uint32_t b_x = ((((uint32_t)(kc * 2) + b_hi) ^ b_rl) << 4);
                const uint32_t bb = sbuf + BOF + b_off + b_x;
                ldsm_x4(&bf[0][0], bb);
                ldsm_x4(&bf[2][0], bb + 16 * ROWA);
                ldsm_x4(&bf[4][0], bb + 32 * ROWA);
                ldsm_x4(&bf[6][0], bb + 48 * ROWA);
            } else {
                const uint32_t row_off = ((uint32_t)(kc * 16) + t_klocal) * 256;
                const uint32_t bb = sbuf + BOF + row_off;
#pragma unroll
                for (int nt = 0; nt < 4; ++nt) {
                    const uint32_t c16 = (uint32_t)(wn * 8 + nt * 2) + t_hi;
                    ldsm_x4_t(&bf[nt * 2][0], bb + ((c16 ^ t_rl) << 4));
                }
            }
#pragma unroll
            for (int mt = 0; mt < 4; ++mt)
#pragma unroll
                for (int nt = 0; nt < 8; ++nt) mma_f16(acc[mt][nt], af[mt], bf[nt]);
        }
        __syncthreads();
    }

    const int qrow = lane >> 2;
    const int qcol = (lane & 3) * 2;

    if (MODE == 3) {
        float* psum = reinterpret_cast<float*>(smem);
        float rsloc[4][2];
#pragma unroll
        for (int mt = 0; mt < 4; ++mt) { rsloc[mt][0] = 0.f; rsloc[mt][1] = 0.f; }

#pragma unroll
        for (int mt = 0; mt < 4; ++mt) {
            const int r0 = m0 + wm * 64 + mt * 16 + qrow;
#pragma unroll
            for (int nt = 0; nt < 8; ++nt) {
                const int ncol = n0 + wn * 64 + nt * 8 + qcol;
                const float* c = acc[mt][nt];
                const float e0 = __expf(alpha * c[0]);
                const float e1 = __expf(alpha * c[1]);
                const float e2 = __expf(alpha * c[2]);
                const float e3 = __expf(alpha * c[3]);
                rsloc[mt][0] += e0 + e1;
                rsloc[mt][1] += e2 + e3;
                size_t off = (size_t)z * zC + (size_t)r0 * N + ncol;
                *reinterpret_cast<uint32_t*>(o0 + off) = pack_h2(e0, e1);
                *reinterpret_cast<uint32_t*>(o0 + off + (size_t)8 * N) = pack_h2(e2, e3);
            }
        }
#pragma unroll
        for (int mt = 0; mt < 4; ++mt)
#pragma unroll
            for (int h = 0; h < 2; ++h) {
                float v = rsloc[mt][h];
                v += __shfl_xor_sync(0xffffffffu, v, 1);
                v += __shfl_xor_sync(0xffffffffu, v, 2);
                rsloc[mt][h] = v;
            }
        if ((lane & 3) == 0) {
#pragma unroll
            for (int mt = 0; mt < 4; ++mt) {
                const int lr = wm * 64 + mt * 16 + qrow;
                psum[wn * GBM + lr] = rsloc[mt][0];
                psum[wn * GBM + lr + 8] = rsloc[mt][1];
            }
        }
        __syncthreads();
        if (tid < GBM) {
            const float s = psum[tid] + psum[GBM + tid];
            part[((size_t)z * M + m0 + tid) * gridDim.x + blockIdx.x] = s;
        }
        return;
    }

#pragma unroll
    for (int mt = 0; mt < 4; ++mt) {
        const int r0 = m0 + wm * 64 + mt * 16 + qrow;
        float sc0 = alpha, sc1 = alpha;
        if (MODE == 2) {
            sc0 = alpha / __ldg(&rsum[(size_t)z * M + r0]);
            sc1 = alpha / __ldg(&rsum[(size_t)z * M + r0 + 8]);
        }
#pragma unroll
        for (int nt = 0; nt < 8; ++nt) {
            const int ncol = n0 + wn * 64 + nt * 8 + qcol;
            const float* c = acc[mt][nt];
            if (MODE == 2) {
                float* base = Cf + (size_t)z * zC;
                float2 v0 = make_float2(sc0 * c[0], sc0 * c[1]);
                float2 v1 = make_float2(sc1 * c[2], sc1 * c[3]);
                *reinterpret_cast<float2*>(base + (size_t)r0 * N + ncol) = v0;
                *reinterpret_cast<float2*>(base + (size_t)(r0 + 8) * N + ncol) = v1;
            } else {   // MODE 1
                const int sel = ncol >> 10;
                __half* D = (sel == 0) ? o0 : ((sel == 1) ? o1 : o2);
                const int cm = ncol & (DD - 1);
                size_t off = (size_t)r0 * DD + cm;
                *reinterpret_cast<uint32_t*>(D + off) = pack_h2(c[0], c[1]);
                *reinterpret_cast<uint32_t*>(D + off + (size_t)8 * DD) = pack_h2(c[2], c[3]);
            }
        }
    }
}

// ---------------- aux kernels ----------------
__global__ __launch_bounds__(256)
void conv_x(const float* __restrict__ in, __half* __restrict__ o, size_t n4)
{
    size_t i = (size_t)blockIdx.x * 256 + threadIdx.x;
    if (i >= n4) return;
    float4 v = reinterpret_cast<const float4*>(in)[i];
    reinterpret_cast<uint2*>(o)[i] = make_uint2(pack_h2(v.x, v.y), pack_h2(v.z, v.w));
}

// convert W [D,D] fp32 -> fused [K=1024, N=3072] fp16 (no transpose)
__global__ __launch_bounds__(256)
void conv_w(const float* __restrict__ Wq, const float* __restrict__ Wk,
            const float* __restrict__ Wv, __half* __restrict__ wt)
{
    const int zz = blockIdx.y;
    const float* W = (zz == 0) ? Wq : ((zz == 1) ? Wk : Wv);
    size_t i = (size_t)blockIdx.x * 256 + threadIdx.x;    // over DD*DD/4
    if (i >= (size_t)DD * DD / 4) return;
    const int k = (int)(i / (DD / 4));
    const int nq = (int)(i % (DD / 4));
    float4 v = reinterpret_cast<const float4*>(W)[i];
    uint2 pk = make_uint2(pack_h2(v.x, v.y), pack_h2(v.z, v.w));
    *reinterpret_cast<uint2*>(wt + (size_t)k * (3 * DD) + zz * DD + nq * 4) = pk;
}

__global__ __launch_bounds__(256)
void reduce_rsum(const float* __restrict__ part, float* __restrict__ rsum)
{
    const int row = blockIdx.x * 8 + (threadIdx.x >> 5);
    const int lane = threadIdx.x & 31;
    float v = part[(size_t)row * 32 + lane];
#pragma unroll
    for (int o = 16; o > 0; o >>= 1) v += __shfl_xor_sync(0xffffffffu, v, o);
    if (lane == 0) rsum[row] = v;
}

// ---------------- launch ----------------
extern "C" void kernel_launch(void* const* d_in, const int* in_sizes, int n_in,
                              void* d_out, int out_size)
{
    const float* x  = (const float*)d_in[0];
    const float* Wq = (const float*)d_in[1];
    const float* Wk = (const float*)d_in[2];
    const float* Wv = (const float*)d_in[3];
    float* out = (float*)d_out;

    __half *px, *pw, *pq, *pk, *pv, *pp;
    float *prs, *ppart;
    cudaGetSymbolAddress((void**)&px, g_x16);   cudaGetSymbolAddress((void**)&pw, g_w16);
    cudaGetSymbolAddress((void**)&pq, g_q16);   cudaGetSymbolAddress((void**)&pk, g_k16);
    cudaGetSymbolAddress((void**)&pv, g_v16);   cudaGetSymbolAddress((void**)&pp, g_p16);
    cudaGetSymbolAddress((void**)&prs, g_rsum); cudaGetSymbolAddress((void**)&ppart, g_part);

    cudaFuncSetAttribute((const void*)tc_gemm<1,false>, cudaFuncAttributeMaxDynamicSharedMemorySize, GEMM_SMEM);
    cudaFuncSetAttribute((const void*)tc_gemm<3,true>,  cudaFuncAttributeMaxDynamicSharedMemorySize, GEMM_SMEM);
    cudaFuncSetAttribute((const void*)tc_gemm<2,false>, cudaFuncAttributeMaxDynamicSharedMemorySize, GEMM_SMEM);

    // 1) convert inputs to fp16 (W without transpose: [K, 3N] fused)
    conv_x<<<(unsigned)(((size_t)MPROJ * DD / 4 + 255) / 256), 256>>>(x, px, (size_t)MPROJ * DD / 4);
    conv_w<<<dim3((unsigned)(((size_t)DD * DD / 4 + 255) / 256), 3), 256>>>(Wq, Wk, Wv, pw);

    // 2) fused QKV projection (NN: B = W [1024, 3072]) -> Q,K,V fp16
    tc_gemm<1,false><<<dim3(3 * DD / GBN, MPROJ / GBM, 1), NTHREADS, GEMM_SMEM>>>(
        px, pw, nullptr, pq, pk, pv,
        MPROJ, 3 * DD, DD, DD, 3 * DD, 0, 0, 0, 1.0f, nullptr, nullptr);

    // 3) QK^T (NT) + fused exp + row partial sums
    tc_gemm<3,true><<<dim3(SS / GBN, SS / GBM, BB), NTHREADS, GEMM_SMEM>>>(
        pq, pk, nullptr, pp, nullptr, nullptr,
        SS, SS, DD, DD, DD,
        (size_t)SS * DD, (size_t)SS * DD, (size_t)SS * SS, 1.0f / 32.0f, nullptr, ppart);

    // 4) reduce partials -> rsum
    reduce_rsum<<<BB * SS / 8, 256>>>(ppart, prs);

    // 5) out = (P @ V) / rsum per batch (NN: B = V [S, D])
    tc_gemm<2,false><<<dim3(DD / GBN, SS / GBM, BB), NTHREADS, GEMM_SMEM>>>(
        pp, pv, out, nullptr, nullptr, nullptr,
        SS, DD, SS, SS, DD,
        (size_t)SS * SS, (size_t)SS * DD, (size_t)SS * DD, 1.0f, prs, ppart);
}

// round 16
// speedup vs baseline: 1.0312x; 1.0312x over previous
#include <cuda_runtime.h>
#include <cuda_fp16.h>
#include <stdint.h>
#include <math.h>

#define BB 4
#define SS 4096
#define DD 1024
#define MPROJ (BB*SS)

// ---------------- device scratch ----------------
__device__ __half g_x16[(size_t)MPROJ*DD];
__device__ __half g_w16[(size_t)DD*3*DD];        // [K=1024, N=3072] = [Wq|Wk|Wv] cols
__device__ __half g_q16[(size_t)MPROJ*DD];
__device__ __half g_k16[(size_t)MPROJ*DD];
__device__ __half g_v16[(size_t)MPROJ*DD];
__device__ __half g_p16[(size_t)BB*SS*SS];
__device__ float  g_part[(size_t)BB*SS*32];
__device__ float  g_rsum[(size_t)BB*SS];

// ---------------- PTX helpers (sm_80-level; no 'a'-suffix features) ----------------
__device__ __forceinline__ uint32_t smem_u32(const void* p) {
    uint32_t a;
    asm("{ .reg .u64 t; cvta.to.shared.u64 t, %1; cvt.u32.u64 %0, t; }" : "=r"(a) : "l"(p));
    return a;
}
__device__ __forceinline__ void cp_async16(uint32_t dst, const void* src) {
    asm volatile("cp.async.cg.shared.global [%0], [%1], 16;" :: "r"(dst), "l"(src));
}
__device__ __forceinline__ void cp_commit() {
    asm volatile("cp.async.commit_group;" ::: "memory");
}
template <int N>
__device__ __forceinline__ void cp_wait() {
    asm volatile("cp.async.wait_group %0;" :: "n"(N) : "memory");
}
__device__ __forceinline__ void ldsm_x4(uint32_t* r, uint32_t addr) {
    asm volatile("ldmatrix.sync.aligned.m8n8.x4.shared.b16 {%0,%1,%2,%3}, [%4];"
                 : "=r"(r[0]), "=r"(r[1]), "=r"(r[2]), "=r"(r[3]) : "r"(addr));
}
__device__ __forceinline__ void ldsm_x4_t(uint32_t* r, uint32_t addr) {
    asm volatile("ldmatrix.sync.aligned.m8n8.x4.trans.shared.b16 {%0,%1,%2,%3}, [%4];"
                 : "=r"(r[0]), "=r"(r[1]), "=r"(r[2]), "=r"(r[3]) : "r"(addr));
}
__device__ __forceinline__ void mma_f16(float* c, const uint32_t* a, const uint32_t* b) {
    asm volatile(
        "mma.sync.aligned.m16n8k16.row.col.f32.f16.f16.f32 "
        "{%0,%1,%2,%3}, {%4,%5,%6,%7}, {%8,%9}, {%0,%1,%2,%3};"
        : "+f"(c[0]), "+f"(c[1]), "+f"(c[2]), "+f"(c[3])
        : "r"(a[0]), "r"(a[1]), "r"(a[2]), "r"(a[3]), "r"(b[0]), "r"(b[1]));
}
__device__ __forceinline__ uint32_t pack_h2(float v0, float v1) {
    __half h0 = __float2half_rn(v0);
    __half h1 = __float2half_rn(v1);
    return (uint32_t)__half_as_ushort(h0) | ((uint32_t)__half_as_ushort(h1) << 16);
}

// ===== GEMM: CTA 128x128, BK=64, 2 stages, 2 CTAs/SM =====
// MT = m-tiles per warp (16 rows each); warps = 8/(MT/2); NTH = 512/MT
//   MT=2: 8 warps (4x2), warp 32x64, 256 threads  (best for epilogue-heavy phases)
//   MT=4: 4 warps (2x2), warp 64x64, 128 threads  (best for mainloop-bound QK)
// TRB=true : B is [N,K] row-major (NT); TRB=false: B is [K,N] row-major (NN, ldsm.trans)
#define GBM 128
#define GBN 128
#define GBK 64
#define ROWA 128               // bytes per A smem row (64 fp16)
#define ABYTES (GBM*ROWA)      // 16384
#define BOF ABYTES
#define BBYTES 16384
#define STAGEB (ABYTES + BBYTES)   // 32768
#define GEMM_SMEM (2*STAGEB)       // 65536

template <bool TRB, int NTH>
__device__ __forceinline__ void stage_in(
    const __half* A, const __half* B,
    int ldA, int ldB, int m0, int n0, int k0, uint32_t sb, int tid)
{
#pragma unroll
    for (int i = 0; i < 1024 / NTH; ++i) {    // A: 128 rows x 8 chunks of 16B
        const int idx = tid + i * NTH;
        const int r = idx >> 3, c16 = idx & 7;
        const uint32_t soff = (uint32_t)(r * ROWA + (((c16 ^ (r & 7)) << 4)));
        cp_async16(sb + soff, A + (size_t)(m0 + r) * ldA + k0 + c16 * 8);
    }
    if (TRB) {
#pragma unroll
        for (int i = 0; i < 1024 / NTH; ++i) {   // B: 128 n-rows x 8 chunks
            const int idx = tid + i * NTH;
            const int r = idx >> 3, c16 = idx & 7;
            const uint32_t soff = (uint32_t)(r * ROWA + (((c16 ^ (r & 7)) << 4)));
            cp_async16(sb + BOF + soff, B + (size_t)(n0 + r) * ldB + k0 + c16 * 8);
        }
    } else {
#pragma unroll
        for (int i = 0; i < 1024 / NTH; ++i) {   // B: 64 k-rows x 16 chunks (256B rows)
            const int idx = tid + i * NTH;
            const int r = idx >> 4, c16 = idx & 15;
            const uint32_t soff = (uint32_t)(r * 256 + (((c16 ^ (r & 7)) << 4)));
            cp_async16(sb + BOF + soff, B + (size_t)(k0 + r) * ldB + n0 + c16 * 8);
        }
    }
}

// MODE 1: fp16 outputs routed among q/k/v by global n / 1024 (projection)
// MODE 2: C fp32 = alpha * D / rsum[row]  (PV)
// MODE 3: P = exp(alpha*D) fp16 + per-(row,ctaX) partial sums (QK+softmax)
template <int MODE, bool TRB, int MT>
__global__ void __launch_bounds__(512 / MT, 2)
tc_gemm(const __half* __restrict__ A, const __half* __restrict__ B,
        float* __restrict__ Cf,
        __half* __restrict__ o0, __half* __restrict__ o1, __half* __restrict__ o2,
        int M, int N, int K, int ldA, int ldB,
        size_t zA, size_t zB, size_t zC,
        float alpha, const float* __restrict__ rsum, float* __restrict__ part)
{
    constexpr int NTH = 512 / MT;
    constexpr int WROWS = 16 * MT;            // rows per warp

    extern __shared__ __align__(128) char smem[];
    const uint32_t sbase = smem_u32(smem);
    const int tid = threadIdx.x;
    const int wid = tid >> 5, lane = tid & 31;
    const int wm = wid >> 1, wn = wid & 1;
    const int z = blockIdx.z;
    const int m0 = blockIdx.y * GBM, n0 = blockIdx.x * GBN;

    A += (size_t)z * zA;  B += (size_t)z * zB;

    float acc[MT][8][4];
#pragma unroll
    for (int i = 0; i < MT; ++i)
#pragma unroll
        for (int j = 0; j < 8; ++j)
#pragma unroll
            for (int q = 0; q < 4; ++q) acc[i][j][q] = 0.f;

    const int numT = K / GBK;
    stage_in<TRB, NTH>(A, B, ldA, ldB, m0, n0, 0, sbase, tid);
    cp_commit();

    // A fragment addressing (plain ldsm)
    const int a_row = wm * WROWS + (lane & 15);
    const uint32_t a_rl = (uint32_t)(a_row & 7);
    const uint32_t a_hi4 = (uint32_t)(lane >> 4);
    const uint32_t a_off = (uint32_t)(a_row * ROWA);

    // B fragment addressing — NT path
    const int b_row = wn * 64 + ((lane >> 4) & 1) * 8 + (lane & 7);
    const uint32_t b_rl = (uint32_t)(b_row & 7);
    const uint32_t b_hi = (uint32_t)((lane >> 3) & 1);
    const uint32_t b_off = (uint32_t)(b_row * ROWA);

    // B fragment addressing — NN (trans) path
    const uint32_t t_klocal = (uint32_t)(((lane >> 3) & 1) * 8 + (lane & 7));
    const uint32_t t_rl = (uint32_t)(lane & 7);
    const uint32_t t_hi = (uint32_t)(lane >> 4);

    for (int t = 0; t < numT; ++t) {
        if (t + 1 < numT) {
            stage_in<TRB, NTH>(A, B, ldA, ldB, m0, n0, (t + 1) * GBK,
                               sbase + ((t + 1) & 1) * STAGEB, tid);
            cp_commit();
            cp_wait<1>();
        } else {
            cp_wait<0>();
        }
        __syncthreads();

        const uint32_t sbuf = sbase + (t & 1) * STAGEB;
#pragma unroll
        for (int kc = 0; kc < 4; ++kc) {
            uint32_t af[MT][4], bf[8][2];
            const uint32_t a_x = ((((uint32_t)(kc * 2) + a_hi4) ^ a_rl) << 4);
#pragma unroll
            for (int mt = 0; mt < MT; ++mt)
                ldsm_x4(af[mt], sbuf + a_off + a_x + mt * (16 * ROWA));

            if (TRB) {
                const uint32_t b_x = ((((uint32_t)(kc * 2) + b_hi) ^ b_rl) << 4);
                const uint32_t bb = sbuf + BOF + b_off + b_x;
                ldsm_x4(&bf[0][0], bb);
                ldsm_x4(&bf[2][0], bb + 16 * ROWA);
                ldsm_x4(&bf[4][0], bb + 32 * ROWA);
                ldsm_x4(&bf[6][0], bb + 48 * ROWA);
            } else {
                const uint32_t row_off = ((uint32_t)(kc * 16) + t_klocal) * 256;
                const uint32_t bb = sbuf + BOF + row_off;
#pragma unroll
                for (int nt = 0; nt < 4; ++nt) {
                    const uint32_t c16 = (uint32_t)(wn * 8 + nt * 2) + t_hi;
                    ldsm_x4_t(&bf[nt * 2][0], bb + ((c16 ^ t_rl) << 4));
                }
            }
#pragma unroll
            for (int mt = 0; mt < MT; ++mt)
#pragma unroll
                for (int nt = 0; nt < 8; ++nt) mma_f16(acc[mt][nt], af[mt], bf[nt]);
        }
        __syncthreads();
    }

    const int qrow = lane >> 2;
    const int qcol = (lane & 3) * 2;

    if (MODE == 3) {
        float* psum = reinterpret_cast<float*>(smem);
        float rsloc[MT][2];
#pragma unroll
        for (int mt = 0; mt < MT; ++mt) { rsloc[mt][0] = 0.f; rsloc[mt][1] = 0.f; }

#pragma unroll
        for (int mt = 0; mt < MT; ++mt) {
            const int r0 = m0 + wm * WROWS + mt * 16 + qrow;
#pragma unroll
            for (int nt = 0; nt < 8; ++nt) {
                const int ncol = n0 + wn * 64 + nt * 8 + qcol;
                const float* c = acc[mt][nt];
                const float e0 = __expf(alpha * c[0]);
                const float e1 = __expf(alpha * c[1]);
                const float e2 = __expf(alpha * c[2]);
                const float e3 = __expf(alpha * c[3]);
                rsloc[mt][0] += e0 + e1;
                rsloc[mt][1] += e2 + e3;
                size_t off = (size_t)z * zC + (size_t)r0 * N + ncol;
                *reinterpret_cast<uint32_t*>(o0 + off) = pack_h2(e0, e1);
                *reinterpret_cast<uint32_t*>(o0 + off + (size_t)8 * N) = pack_h2(e2, e3);
            }
        }
#pragma unroll
        for (int mt = 0; mt < MT; ++mt)
#pragma unroll
            for (int h = 0; h < 2; ++h) {
                float v = rsloc[mt][h];
                v += __shfl_xor_sync(0xffffffffu, v, 1);
                v += __shfl_xor_sync(0xffffffffu, v, 2);
                rsloc[mt][h] = v;
            }
        if ((lane & 3) == 0) {
#pragma unroll
            for (int mt = 0; mt < MT; ++mt) {
                const int lr = wm * WROWS + mt * 16 + qrow;
                psum[wn * GBM + lr] = rsloc[mt][0];
                psum[wn * GBM + lr + 8] = rsloc[mt][1];
            }
        }
        __syncthreads();
        if (tid < GBM) {
            const float s = psum[tid] + psum[GBM + tid];
            part[((size_t)z * M + m0 + tid) * gridDim.x + blockIdx.x] = s;
        }
        return;
    }

#pragma unroll
    for (int mt = 0; mt < MT; ++mt) {
        const int r0 = m0 + wm * WROWS + mt * 16 + qrow;
        float sc0 = alpha, sc1 = alpha;
        if (MODE == 2) {
            sc0 = alpha / __ldg(&rsum[(size_t)z * M + r0]);
            sc1 = alpha / __ldg(&rsum[(size_t)z * M + r0 + 8]);
        }
#pragma unroll
        for (int nt = 0; nt < 8; ++nt) {
            const int ncol = n0 + wn * 64 + nt * 8 + qcol;
            const float* c = acc[mt][nt];
            if (MODE == 2) {
                float* base = Cf + (size_t)z * zC;
                float2 v0 = make_float2(sc0 * c[0], sc0 * c[1]);
                float2 v1 = make_float2(sc1 * c[2], sc1 * c[3]);
                *reinterpret_cast<float2*>(base + (size_t)r0 * N + ncol) = v0;
                *reinterpret_cast<float2*>(base + (size_t)(r0 + 8) * N + ncol) = v1;
            } else {   // MODE 1
                const int sel = ncol >> 10;
                __half* D = (sel == 0) ? o0 : ((sel == 1) ? o1 : o2);
                const int cm = ncol & (DD - 1);
                size_t off = (size_t)r0 * DD + cm;
                *reinterpret_cast<uint32_t*>(D + off) = pack_h2(c[0], c[1]);
                *reinterpret_cast<uint32_t*>(D + off + (size_t)8 * DD) = pack_h2(c[2], c[3]);
            }
        }
    }
}

// ---------------- aux kernels ----------------
__global__ __launch_bounds__(256)
void conv_x(const float* __restrict__ in, __half* __restrict__ o, size_t n4)
{
    size_t i = (size_t)blockIdx.x * 256 + threadIdx.x;
    if (i >= n4) return;
    float4 v = reinterpret_cast<const float4*>(in)[i];
    reinterpret_cast<uint2*>(o)[i] = make_uint2(pack_h2(v.x, v.y), pack_h2(v.z, v.w));
}

// convert W [D,D] fp32 -> fused [K=1024, N=3072] fp16 (no transpose)
__global__ __launch_bounds__(256)
void conv_w(const float* __restrict__ Wq, const float* __restrict__ Wk,
            const float* __restrict__ Wv, __half* __restrict__ wt)
{
    const int zz = blockIdx.y;
    const float* W = (zz == 0) ? Wq : ((zz == 1) ? Wk : Wv);
    size_t i = (size_t)blockIdx.x * 256 + threadIdx.x;    // over DD*DD/4
    if (i >= (size_t)DD * DD / 4) return;
    const int k = (int)(i / (DD / 4));
    const int nq = (int)(i % (DD / 4));
    float4 v = reinterpret_cast<const float4*>(W)[i];
    uint2 pk = make_uint2(pack_h2(v.x, v.y), pack_h2(v.z, v.w));
    *reinterpret_cast<uint2*>(wt + (size_t)k * (3 * DD) + zz * DD + nq * 4) = pk;
}

__global__ __launch_bounds__(256)
void reduce_rsum(const float* __restrict__ part, float* __restrict__ rsum)
{
    const int row = blockIdx.x * 8 + (threadIdx.x >> 5);
    const int lane = threadIdx.x & 31;
    float v = part[(size_t)row * 32 + lane];
#pragma unroll
    for (int o = 16; o > 0; o >>= 1) v += __shfl_xor_sync(0xffffffffu, v, o);
    if (lane == 0) rsum[row] = v;
}

// ---------------- launch ----------------
extern "C" void kernel_launch(void* const* d_in, const int* in_sizes, int n_in,
                              void* d_out, int out_size)
{
    const float* x  = (const float*)d_in[0];
    const float* Wq = (const float*)d_in[1];
    const float* Wk = (const float*)d_in[2];
    const float* Wv = (const float*)d_in[3];
    float* out = (float*)d_out;

    __half *px, *pw, *pq, *pk, *pv, *pp;
    float *prs, *ppart;
    cudaGetSymbolAddress((void**)&px, g_x16);   cudaGetSymbolAddress((void**)&pw, g_w16);
    cudaGetSymbolAddress((void**)&pq, g_q16);   cudaGetSymbolAddress((void**)&pk, g_k16);
    cudaGetSymbolAddress((void**)&pv, g_v16);   cudaGetSymbolAddress((void**)&pp, g_p16);
    cudaGetSymbolAddress((void**)&prs, g_rsum); cudaGetSymbolAddress((void**)&ppart, g_part);

    cudaFuncSetAttribute((const void*)tc_gemm<1,false,2>, cudaFuncAttributeMaxDynamicSharedMemorySize, GEMM_SMEM);
    cudaFuncSetAttribute((const void*)tc_gemm<3,true,4>,  cudaFuncAttributeMaxDynamicSharedMemorySize, GEMM_SMEM);
    cudaFuncSetAttribute((const void*)tc_gemm<2,false,2>, cudaFuncAttributeMaxDynamicSharedMemorySize, GEMM_SMEM);

    // 1) convert inputs to fp16 (W without transpose: [K, 3N] fused)
    conv_x<<<(unsigned)(((size_t)MPROJ * DD / 4 + 255) / 256), 256>>>(x, px, (size_t)MPROJ * DD / 4);
    conv_w<<<dim3((unsigned)(((size_t)DD * DD / 4 + 255) / 256), 3), 256>>>(Wq, Wk, Wv, pw);

    // 2) fused QKV projection (NN, MT=2: 8 warps — best epilogue throughput)
    tc_gemm<1,false,2><<<dim3(3 * DD / GBN, MPROJ / GBM, 1), 256, GEMM_SMEM>>>(
        px, pw, nullptr, pq, pk, pv,
        MPROJ, 3 * DD, DD, DD, 3 * DD, 0, 0, 0, 1.0f, nullptr, nullptr);

    // 3) QK^T (NT, MT=4: 4 warps 64x64 — best mainloop throughput) + fused exp
    tc_gemm<3,true,4><<<dim3(SS / GBN, SS / GBM, BB), 128, GEMM_SMEM>>>(
        pq, pk, nullptr, pp, nullptr, nullptr,
        SS, SS, DD, DD, DD,
        (size_t)SS * DD, (size_t)SS * DD, (size_t)SS * SS, 1.0f / 32.0f, nullptr, ppart);

    // 4) reduce partials -> rsum
    reduce_rsum<<<BB * SS / 8, 256>>>(ppart, prs);

    // 5) out = (P @ V) / rsum per batch (NN, MT=2)
    tc_gemm<2,false,2><<<dim3(DD / GBN, SS / GBM, BB), 256, GEMM_SMEM>>>(
        pp, pv, out, nullptr, nullptr, nullptr,
        SS, DD, SS, SS, DD,
        (size_t)SS * SS, (size_t)SS * DD, (size_t)SS * DD, 1.0f, prs, ppart);
}